// round 6
// baseline (speedup 1.0000x reference)
#include <cuda_runtime.h>
#include <cstddef>

#define KC 16
#define NMAX 100000
#define E2MAX 3200000
#define BP_EPS 1e-12f

// Persistent scratch (device globals; no allocation allowed).
static __device__ float g_lmA[(size_t)E2MAX * KC];  // messages written by iter2
static __device__ float g_lmB[(size_t)E2MAX * KC];  // messages written by iter3
static __device__ float g_S[5][(size_t)NMAX * KC];  // node accumulators (use [1..4])
static __device__ int   g_deg[NMAX];                // in-degree
static __device__ float g_psi[KC * KC];
static __device__ float g_acoef[KC];
static __device__ float g_off;
static __device__ int   g_fast;

__device__ __forceinline__ float ex2f(float x) {
    float y; asm("ex2.approx.f32 %0, %1;" : "=f"(y) : "f"(x)); return y;
}
__device__ __forceinline__ float lg2f_(float x) {
    float y; asm("lg2.approx.f32 %0, %1;" : "=f"(y) : "f"(x)); return y;
}
__device__ __forceinline__ void red_v4(float* p, float a, float b, float c, float d) {
    asm volatile("red.global.add.v4.f32 [%0], {%1, %2, %3, %4};"
                 :: "l"(p), "f"(a), "f"(b), "f"(c), "f"(d) : "memory");
}
__device__ __forceinline__ float quad_sum(float v) {
    v += __shfl_xor_sync(0xFFFFFFFFu, v, 1);
    v += __shfl_xor_sync(0xFFFFFFFFu, v, 2);
    return v;
}

// k0: block 0 computes psi tables; all blocks zero the degree histogram.
__global__ void prep_kernel(const float* __restrict__ logpsi, int n) {
    int t = threadIdx.x;
    if (blockIdx.x == 0) {
        __shared__ float psi[KC * KC];
        if (t < KC * KC) { float p = expf(logpsi[t]); psi[t] = p; g_psi[t] = p; }
        __syncthreads();
        if (t == 0) {
            float off = psi[1];
            int fast = 1;
            for (int i = 0; i < KC; i++)
                for (int j = 0; j < KC; j++)
                    if (i != j && psi[i * KC + j] != off) fast = 0;
            g_fast = fast;
            g_off = off;
            for (int c = 0; c < KC; c++) g_acoef[c] = psi[c * KC + c] - off;
        }
    }
    int i = blockIdx.x * blockDim.x + t;
    if (i < n) g_deg[i] = 0;
}

// k1: degree histogram + init S[1..4] = log2(prior)
__global__ void hist_init_kernel(const int* __restrict__ dst,
                                 const float* __restrict__ prior, int e2, int n16) {
    int i = blockIdx.x * blockDim.x + threadIdx.x;
    if (i < e2) atomicAdd(&g_deg[dst[i]], 1);
    if (i < n16) {
        float v = log2f(prior[i]);
        g_S[1][i] = v; g_S[2][i] = v; g_S[3][i] = v; g_S[4][i] = v;
    }
}

// Message body: given clamped b-slice (4 classes), produce normalized log2 msg.
__device__ __forceinline__ void msg_from_b(
    float b0, float b1, float b2, float b3, int sub,
    const float* __restrict__ s_a, const float* __restrict__ s_psi,
    int fast, float off, int t,
    float& m0, float& m1, float& m2, float& m3)
{
    float T = quad_sum(b0 + b1 + b2 + b3);
    if (fast) {
        float oT = off * T;
        m0 = fmaf(s_a[sub * 4 + 0], b0, oT);
        m1 = fmaf(s_a[sub * 4 + 1], b1, oT);
        m2 = fmaf(s_a[sub * 4 + 2], b2, oT);
        m3 = fmaf(s_a[sub * 4 + 3], b3, oT);
    } else {
        float bl[4] = {b0, b1, b2, b3};
        float acc[4] = {0.f, 0.f, 0.f, 0.f};
        #pragma unroll
        for (int j = 0; j < KC; j++) {
            int owner_sub = j >> 2;
            float bj = __shfl_sync(0xFFFFFFFFu, bl[j & 3], ((t & 31) & ~3) | owner_sub, 32);
            #pragma unroll
            for (int c = 0; c < 4; c++)
                acc[c] = fmaf(bj, s_psi[j * KC + sub * 4 + c], acc[c]);
        }
        m0 = acc[0]; m1 = acc[1]; m2 = acc[2]; m3 = acc[3];
    }
    float Z = quad_sum(m0 + m1 + m2 + m3);
    float lZ = lg2f_(Z);
    m0 = lg2f_(m0) - lZ;
    m1 = lg2f_(m1) - lZ;
    m2 = lg2f_(m2) - lZ;
    m3 = lg2f_(m3) - lZ;
}

// Recompute the iter-1 message slice (4 classes) for direction whose source
// node has prior row P and degree deg: b = max(prior * 2^(4-4deg), EPS).
// Must be the EXACT same op sequence everywhere it's evaluated.
__device__ __forceinline__ void msg1_from_prior(
    float4 P, int deg, int sub,
    const float* __restrict__ s_a, const float* __restrict__ s_psi,
    int fast, float off, int t,
    float& m0, float& m1, float& m2, float& m3)
{
    float w = ex2f(fmaf((float)deg, -4.f, 4.f));
    float b0 = fmaxf(P.x * w, BP_EPS);
    float b1 = fmaxf(P.y * w, BP_EPS);
    float b2 = fmaxf(P.z * w, BP_EPS);
    float b3 = fmaxf(P.w * w, BP_EPS);
    msg_from_b(b0, b1, b2, b3, sub, s_a, s_psi, fast, off, t, m0, m1, m2, m3);
}

#define LOAD_TABLES() \
    __shared__ float s_psi[KC * KC]; \
    __shared__ float s_a[KC]; \
    __shared__ float s_off_sh; \
    __shared__ int   s_fast_sh; \
    { int tt = threadIdx.x; \
      if (tt < KC * KC) s_psi[tt] = g_psi[tt]; \
      if (tt < KC) s_a[tt] = g_acoef[tt]; \
      if (tt == 0) { s_off_sh = g_off; s_fast_sh = g_fast; } } \
    __syncthreads();

// k2: iteration 1. Pair (q, q+E) per quad. NO message store (iter2 recomputes);
// just REDs the iter-1 messages into S[1].
__global__ void __launch_bounds__(256) update_first_kernel(
    const int* __restrict__ src, const int* __restrict__ dst,
    const float* __restrict__ prior, int E)
{
    LOAD_TABLES();
    int t = threadIdx.x;
    int gt = blockIdx.x * blockDim.x + t;
    int q = gt >> 2, sub = t & 3;
    int valid = q < E;
    if (!valid) q = E - 1;

    int s = src[q], d = dst[q];
    float4 Ps = *reinterpret_cast<const float4*>(prior + (size_t)s * KC + sub * 4);
    float4 Pd = *reinterpret_cast<const float4*>(prior + (size_t)d * KC + sub * 4);
    int degs = g_deg[s], degd = g_deg[d];

    const int fast = s_fast_sh; const float off = s_off_sh;

    float m0, m1, m2, m3;   // s -> d
    msg1_from_prior(Ps, degs, sub, s_a, s_psi, fast, off, t, m0, m1, m2, m3);
    float r0, r1, r2, r3;   // d -> s
    msg1_from_prior(Pd, degd, sub, s_a, s_psi, fast, off, t, r0, r1, r2, r3);

    if (valid) {
        red_v4(g_S[1] + (size_t)d * KC + sub * 4, m0, m1, m2, m3);
        red_v4(g_S[1] + (size_t)s * KC + sub * 4, r0, r1, r2, r3);
    }
}

// k3: iteration 2. Recomputes iter-1 messages from prior+deg (L2-resident),
// computes iter-2 messages, stores them to lmA (streaming), REDs into S[2].
__global__ void __launch_bounds__(256) update_second_kernel(
    const int* __restrict__ src, const int* __restrict__ dst,
    const float* __restrict__ prior, int E)
{
    LOAD_TABLES();
    int t = threadIdx.x;
    int gt = blockIdx.x * blockDim.x + t;
    int q = gt >> 2, sub = t & 3;
    int valid = q < E;
    if (!valid) q = E - 1;

    int s = src[q], d = dst[q];
    float4 Ps = *reinterpret_cast<const float4*>(prior + (size_t)s * KC + sub * 4);
    float4 Pd = *reinterpret_cast<const float4*>(prior + (size_t)d * KC + sub * 4);
    int degs = g_deg[s], degd = g_deg[d];
    float4 Ss = *reinterpret_cast<const float4*>(g_S[1] + (size_t)s * KC + sub * 4);
    float4 Sd = *reinterpret_cast<const float4*>(g_S[1] + (size_t)d * KC + sub * 4);

    const int fast = s_fast_sh; const float off = s_off_sh;

    // iter-1 messages of the pair (exact recompute)
    float f0, f1, f2, f3;   // m1: s -> d
    msg1_from_prior(Ps, degs, sub, s_a, s_psi, fast, off, t, f0, f1, f2, f3);
    float g0, g1, g2, g3;   // m1: d -> s
    msg1_from_prior(Pd, degd, sub, s_a, s_psi, fast, off, t, g0, g1, g2, g3);

    // iter-2 message e0 = q (s->d): excludes reverse m1 (d->s) = g
    float a0 = fmaxf(ex2f(Ss.x - g0), BP_EPS);
    float a1 = fmaxf(ex2f(Ss.y - g1), BP_EPS);
    float a2 = fmaxf(ex2f(Ss.z - g2), BP_EPS);
    float a3 = fmaxf(ex2f(Ss.w - g3), BP_EPS);
    float m0, m1, m2, m3;
    msg_from_b(a0, a1, a2, a3, sub, s_a, s_psi, fast, off, t, m0, m1, m2, m3);

    // iter-2 message e1 = q+E (d->s): excludes m1 (s->d) = f
    float c0 = fmaxf(ex2f(Sd.x - f0), BP_EPS);
    float c1 = fmaxf(ex2f(Sd.y - f1), BP_EPS);
    float c2 = fmaxf(ex2f(Sd.z - f2), BP_EPS);
    float c3 = fmaxf(ex2f(Sd.w - f3), BP_EPS);
    float r0, r1, r2, r3;
    msg_from_b(c0, c1, c2, c3, sub, s_a, s_psi, fast, off, t, r0, r1, r2, r3);

    if (valid) {
        __stcs(reinterpret_cast<float4*>(g_lmA + (size_t)q * KC + sub * 4),
               make_float4(m0, m1, m2, m3));
        __stcs(reinterpret_cast<float4*>(g_lmA + ((size_t)q + E) * KC + sub * 4),
               make_float4(r0, r1, r2, r3));
        red_v4(g_S[2] + (size_t)d * KC + sub * 4, m0, m1, m2, m3);
        red_v4(g_S[2] + (size_t)s * KC + sub * 4, r0, r1, r2, r3);
    }
}

// Steady iteration. AB=1: old=lmA,new=lmB. AB=0: old=lmB. LAST: skip store.
template <int AB, int LAST>
__global__ void __launch_bounds__(256) update_kernel(
    const int* __restrict__ src, const int* __restrict__ dst, int sin_idx, int E)
{
    LOAD_TABLES();
    int t = threadIdx.x;
    int gt = blockIdx.x * blockDim.x + t;
    int q = gt >> 2, sub = t & 3;
    int valid = q < E;
    if (!valid) q = E - 1;

    const float* __restrict__ lm_old = AB ? g_lmA : g_lmB;
    float* __restrict__       lm_new = AB ? g_lmB : g_lmA;
    const float* __restrict__ Sin   = g_S[sin_idx];
    float* __restrict__       Snext = g_S[sin_idx + 1];

    int s = src[q], d = dst[q];

    float4 lm0 = __ldcs(reinterpret_cast<const float4*>(lm_old + (size_t)q * KC + sub * 4));
    float4 lm1 = __ldcs(reinterpret_cast<const float4*>(lm_old + ((size_t)q + E) * KC + sub * 4));
    float4 Ss = *reinterpret_cast<const float4*>(Sin + (size_t)s * KC + sub * 4);
    float4 Sd = *reinterpret_cast<const float4*>(Sin + (size_t)d * KC + sub * 4);

    const int fast = s_fast_sh; const float off = s_off_sh;

    // edge e0 = q (s->d): excludes reverse message lm1
    float a0 = fmaxf(ex2f(Ss.x - lm1.x), BP_EPS);
    float a1 = fmaxf(ex2f(Ss.y - lm1.y), BP_EPS);
    float a2 = fmaxf(ex2f(Ss.z - lm1.z), BP_EPS);
    float a3 = fmaxf(ex2f(Ss.w - lm1.w), BP_EPS);
    float m0, m1, m2, m3;
    msg_from_b(a0, a1, a2, a3, sub, s_a, s_psi, fast, off, t, m0, m1, m2, m3);

    // edge e1 = q+E (d->s): excludes reverse message lm0
    float c0 = fmaxf(ex2f(Sd.x - lm0.x), BP_EPS);
    float c1 = fmaxf(ex2f(Sd.y - lm0.y), BP_EPS);
    float c2 = fmaxf(ex2f(Sd.z - lm0.z), BP_EPS);
    float c3 = fmaxf(ex2f(Sd.w - lm0.w), BP_EPS);
    float r0, r1, r2, r3;
    msg_from_b(c0, c1, c2, c3, sub, s_a, s_psi, fast, off, t, r0, r1, r2, r3);

    if (valid) {
        if (!LAST) {
            __stcs(reinterpret_cast<float4*>(lm_new + (size_t)q * KC + sub * 4),
                   make_float4(m0, m1, m2, m3));
            __stcs(reinterpret_cast<float4*>(lm_new + ((size_t)q + E) * KC + sub * 4),
                   make_float4(r0, r1, r2, r3));
        }
        red_v4(Snext + (size_t)d * KC + sub * 4, m0, m1, m2, m3);
        red_v4(Snext + (size_t)s * KC + sub * 4, r0, r1, r2, r3);
    }
}

// beliefs: out = normalize(max(2^S4, EPS)); quad per node.
__global__ void belief_kernel(float* __restrict__ out, int n) {
    int gt  = blockIdx.x * blockDim.x + threadIdx.x;
    int i   = gt >> 2;
    int sub = threadIdx.x & 3;
    if (i >= n) return;
    float4 v = *reinterpret_cast<const float4*>(g_S[4] + (size_t)i * KC + sub * 4);
    float x0 = fmaxf(ex2f(v.x), BP_EPS);
    float x1 = fmaxf(ex2f(v.y), BP_EPS);
    float x2 = fmaxf(ex2f(v.z), BP_EPS);
    float x3 = fmaxf(ex2f(v.w), BP_EPS);
    float Z = quad_sum(x0 + x1 + x2 + x3);
    float r = 1.f / Z;
    *reinterpret_cast<float4*>(out + (size_t)i * KC + sub * 4) =
        make_float4(x0 * r, x1 * r, x2 * r, x3 * r);
}

extern "C" void kernel_launch(void* const* d_in, const int* in_sizes, int n_in,
                              void* d_out, int out_size) {
    const float* prior  = (const float*)d_in[0];
    const float* logpsi = (const float*)d_in[1];
    const int*   src    = (const int*)d_in[2];
    const int*   dst    = (const int*)d_in[3];
    float* out = (float*)d_out;

    int n16 = in_sizes[0];      // n * 16
    int n   = n16 / KC;
    int e2  = in_sizes[2];      // directed edges
    int E   = e2 / 2;           // undirected pairs

    int gb_n    = (n + 255) / 256;
    int gb_e2   = (e2 + 255) / 256;
    int gb_pair = (E * 4 + 255) / 256;   // quad-per-pair grid
    int gb_nq   = (n * 4 + 255) / 256;

    // #0, #1: prelude
    prep_kernel<<<gb_n, 256>>>(logpsi, n);
    hist_init_kernel<<<gb_e2, 256>>>(dst, prior, e2, n16);

    // #2: iteration 1 — no message store, REDs into S1
    update_first_kernel<<<gb_pair, 256>>>(src, dst, prior, E);
    // #3: iteration 2 — recompute m1 from prior/deg, store lmA, S1 -> S2
    update_second_kernel<<<gb_pair, 256>>>(src, dst, prior, E);
    // #4: iteration 3 — lmA -> lmB, S2 -> S3
    update_kernel<1, 0><<<gb_pair, 256>>>(src, dst, 2, E);
    // #5: iteration 4 — read lmB, no store, S3 -> S4
    update_kernel<0, 1><<<gb_pair, 256>>>(src, dst, 3, E);

    // #6: beliefs
    belief_kernel<<<gb_nq, 256>>>(out, n);
}

// round 9
// speedup vs baseline: 1.3612x; 1.3612x over previous
#include <cuda_runtime.h>
#include <cstddef>

#define KC 16
#define NMAX 100000
#define E2MAX 3200000
#define BP_EPS 1e-12f

// Persistent scratch (device globals; no allocation allowed).
// Messages stored as u = b/T in unorm16 (scale-invariant input to msg_from_b).
static __device__ unsigned short g_uA[(size_t)E2MAX * KC];  // 102.4 MB ping
static __device__ unsigned short g_uB[(size_t)E2MAX * KC];  // 102.4 MB pong
static __device__ float g_S[5][(size_t)NMAX * KC];          // node accumulators [1..4]
static __device__ int   g_deg[NMAX];                        // in-degree
static __device__ float g_psi[KC * KC];
static __device__ float g_acoef[KC];
static __device__ float g_off;
static __device__ int   g_fast;

__device__ __forceinline__ float ex2f(float x) {
    float y; asm("ex2.approx.f32 %0, %1;" : "=f"(y) : "f"(x)); return y;
}
__device__ __forceinline__ float lg2f_(float x) {
    float y; asm("lg2.approx.f32 %0, %1;" : "=f"(y) : "f"(x)); return y;
}
__device__ __forceinline__ void red_v4(float* p, float a, float b, float c, float d) {
    asm volatile("red.global.add.v4.f32 [%0], {%1, %2, %3, %4};"
                 :: "l"(p), "f"(a), "f"(b), "f"(c), "f"(d) : "memory");
}
__device__ __forceinline__ float quad_sum(float v) {
    v += __shfl_xor_sync(0xFFFFFFFFu, v, 1);
    v += __shfl_xor_sync(0xFFFFFFFFu, v, 2);
    return v;
}

// k0: block 0 computes psi tables; all blocks zero the degree histogram.
__global__ void prep_kernel(const float* __restrict__ logpsi, int n) {
    int t = threadIdx.x;
    if (blockIdx.x == 0) {
        __shared__ float psi[KC * KC];
        if (t < KC * KC) { float p = expf(logpsi[t]); psi[t] = p; g_psi[t] = p; }
        __syncthreads();
        if (t == 0) {
            float off = psi[1];
            int fast = 1;
            for (int i = 0; i < KC; i++)
                for (int j = 0; j < KC; j++)
                    if (i != j && psi[i * KC + j] != off) fast = 0;
            g_fast = fast;
            g_off = off;
            for (int c = 0; c < KC; c++) g_acoef[c] = psi[c * KC + c] - off;
        }
    }
    int i = blockIdx.x * blockDim.x + t;
    if (i < n) g_deg[i] = 0;
}

// k1: degree histogram + init S[1..4] = log2(prior)
__global__ void hist_init_kernel(const int* __restrict__ dst,
                                 const float* __restrict__ prior, int e2, int n16) {
    int i = blockIdx.x * blockDim.x + threadIdx.x;
    if (i < e2) atomicAdd(&g_deg[dst[i]], 1);
    if (i < n16) {
        float v = log2f(prior[i]);
        g_S[1][i] = v; g_S[2][i] = v; g_S[3][i] = v; g_S[4][i] = v;
    }
}

// Core message transform (scale-invariant in b): given b-slice (4 classes),
// produce normalized log2 message slice m = log2((b @ psi) / sum).
__device__ __forceinline__ void msg_from_b(
    float b0, float b1, float b2, float b3, int sub,
    const float* __restrict__ s_a, const float* __restrict__ s_psi,
    int fast, float off, int t,
    float& m0, float& m1, float& m2, float& m3)
{
    float T = quad_sum(b0 + b1 + b2 + b3);
    if (fast) {
        float oT = off * T;
        m0 = fmaf(s_a[sub * 4 + 0], b0, oT);
        m1 = fmaf(s_a[sub * 4 + 1], b1, oT);
        m2 = fmaf(s_a[sub * 4 + 2], b2, oT);
        m3 = fmaf(s_a[sub * 4 + 3], b3, oT);
    } else {
        float bl[4] = {b0, b1, b2, b3};
        float acc[4] = {0.f, 0.f, 0.f, 0.f};
        #pragma unroll
        for (int j = 0; j < KC; j++) {
            int owner_sub = j >> 2;
            float bj = __shfl_sync(0xFFFFFFFFu, bl[j & 3], ((t & 31) & ~3) | owner_sub, 32);
            #pragma unroll
            for (int c = 0; c < 4; c++)
                acc[c] = fmaf(bj, s_psi[j * KC + sub * 4 + c], acc[c]);
        }
        m0 = acc[0]; m1 = acc[1]; m2 = acc[2]; m3 = acc[3];
    }
    float Z = quad_sum(m0 + m1 + m2 + m3);
    float lZ = lg2f_(Z);
    m0 = lg2f_(m0) - lZ;
    m1 = lg2f_(m1) - lZ;
    m2 = lg2f_(m2) - lZ;
    m3 = lg2f_(m3) - lZ;
}

// Encode a clamped b-slice as u = b/T in unorm16 (T = quad sum, scale factor).
__device__ __forceinline__ ushort4 enc_u(float b0, float b1, float b2, float b3) {
    float T = quad_sum(b0 + b1 + b2 + b3);
    float r = 65535.f / T;
    ushort4 o;
    o.x = (unsigned short)__float2uint_rn(fminf(b0 * r, 65535.f));
    o.y = (unsigned short)__float2uint_rn(fminf(b1 * r, 65535.f));
    o.z = (unsigned short)__float2uint_rn(fminf(b2 * r, 65535.f));
    o.w = (unsigned short)__float2uint_rn(fminf(b3 * r, 65535.f));
    return o;
}

#define LOAD_TABLES() \
    __shared__ float s_psi[KC * KC]; \
    __shared__ float s_a[KC]; \
    __shared__ float s_off_sh; \
    __shared__ int   s_fast_sh; \
    { int tt = threadIdx.x; \
      if (tt < KC * KC) s_psi[tt] = g_psi[tt]; \
      if (tt < KC) s_a[tt] = g_acoef[tt]; \
      if (tt == 0) { s_off_sh = g_off; s_fast_sh = g_fast; } } \
    __syncthreads();

// k2: iteration 1. Pair (q, q+E) per quad. b1 = max(prior * 2^(4-4deg), EPS).
// Stores u (compressed b) to uB and REDs the iter-1 log2 messages into S[1].
__global__ void __launch_bounds__(256) update_first_kernel(
    const int* __restrict__ src, const int* __restrict__ dst,
    const float* __restrict__ prior, int E)
{
    LOAD_TABLES();
    int t = threadIdx.x;
    int gt = blockIdx.x * blockDim.x + t;
    int q = gt >> 2, sub = t & 3;
    int valid = q < E;
    if (!valid) q = E - 1;

    int s = src[q], d = dst[q];
    float4 Ps = *reinterpret_cast<const float4*>(prior + (size_t)s * KC + sub * 4);
    float4 Pd = *reinterpret_cast<const float4*>(prior + (size_t)d * KC + sub * 4);
    float ws = ex2f(fmaf((float)g_deg[s], -4.f, 4.f));
    float wd = ex2f(fmaf((float)g_deg[d], -4.f, 4.f));

    const int fast = s_fast_sh; const float off = s_off_sh;

    // e0 = q: s -> d
    float a0 = fmaxf(Ps.x * ws, BP_EPS), a1 = fmaxf(Ps.y * ws, BP_EPS);
    float a2 = fmaxf(Ps.z * ws, BP_EPS), a3 = fmaxf(Ps.w * ws, BP_EPS);
    float m0, m1, m2, m3;
    msg_from_b(a0, a1, a2, a3, sub, s_a, s_psi, fast, off, t, m0, m1, m2, m3);
    ushort4 ue0 = enc_u(a0, a1, a2, a3);

    // e1 = q+E: d -> s
    float c0 = fmaxf(Pd.x * wd, BP_EPS), c1 = fmaxf(Pd.y * wd, BP_EPS);
    float c2 = fmaxf(Pd.z * wd, BP_EPS), c3 = fmaxf(Pd.w * wd, BP_EPS);
    float r0, r1, r2, r3;
    msg_from_b(c0, c1, c2, c3, sub, s_a, s_psi, fast, off, t, r0, r1, r2, r3);
    ushort4 ue1 = enc_u(c0, c1, c2, c3);

    if (valid) {
        *reinterpret_cast<ushort4*>(g_uB + (size_t)q * KC + sub * 4) = ue0;
        *reinterpret_cast<ushort4*>(g_uB + ((size_t)q + E) * KC + sub * 4) = ue1;
        red_v4(g_S[1] + (size_t)d * KC + sub * 4, m0, m1, m2, m3);
        red_v4(g_S[1] + (size_t)s * KC + sub * 4, r0, r1, r2, r3);
    }
}

// Steady iteration. AB=1: old=uA,new=uB. AB=0: old=uB,new=uA. LAST: skip store.
// Reconstructs previous log2 messages from compressed u via the identical
// (scale-invariant) msg_from_b transform.
template <int AB, int LAST>
__global__ void __launch_bounds__(256) update_kernel(
    const int* __restrict__ src, const int* __restrict__ dst, int sin_idx, int E)
{
    LOAD_TABLES();
    int t = threadIdx.x;
    int gt = blockIdx.x * blockDim.x + t;
    int q = gt >> 2, sub = t & 3;
    int valid = q < E;
    if (!valid) q = E - 1;

    const unsigned short* __restrict__ u_old = AB ? g_uA : g_uB;
    unsigned short* __restrict__       u_new = AB ? g_uB : g_uA;
    const float* __restrict__ Sin   = g_S[sin_idx];
    float* __restrict__       Snext = g_S[sin_idx + 1];

    int s = src[q], d = dst[q];

    ushort4 up0 = *reinterpret_cast<const ushort4*>(u_old + (size_t)q * KC + sub * 4);
    ushort4 up1 = *reinterpret_cast<const ushort4*>(u_old + ((size_t)q + E) * KC + sub * 4);
    float4 Ss = *reinterpret_cast<const float4*>(Sin + (size_t)s * KC + sub * 4);
    float4 Sd = *reinterpret_cast<const float4*>(Sin + (size_t)d * KC + sub * 4);

    const int fast = s_fast_sh; const float off = s_off_sh;
    const float dec = 1.f / 65535.f;

    // reconstruct old log2 messages of the pair
    float l00, l01, l02, l03;  // lm_old e0 (s->d)
    msg_from_b(up0.x * dec, up0.y * dec, up0.z * dec, up0.w * dec,
               sub, s_a, s_psi, fast, off, t, l00, l01, l02, l03);
    float l10, l11, l12, l13;  // lm_old e1 (d->s)
    msg_from_b(up1.x * dec, up1.y * dec, up1.z * dec, up1.w * dec,
               sub, s_a, s_psi, fast, off, t, l10, l11, l12, l13);

    // new message e0 = q (s->d): excludes reverse message (e1)
    float a0 = fmaxf(ex2f(Ss.x - l10), BP_EPS);
    float a1 = fmaxf(ex2f(Ss.y - l11), BP_EPS);
    float a2 = fmaxf(ex2f(Ss.z - l12), BP_EPS);
    float a3 = fmaxf(ex2f(Ss.w - l13), BP_EPS);
    float m0, m1, m2, m3;
    msg_from_b(a0, a1, a2, a3, sub, s_a, s_psi, fast, off, t, m0, m1, m2, m3);

    // new message e1 = q+E (d->s): excludes reverse message (e0)
    float c0 = fmaxf(ex2f(Sd.x - l00), BP_EPS);
    float c1 = fmaxf(ex2f(Sd.y - l01), BP_EPS);
    float c2 = fmaxf(ex2f(Sd.z - l02), BP_EPS);
    float c3 = fmaxf(ex2f(Sd.w - l03), BP_EPS);
    float r0, r1, r2, r3;
    msg_from_b(c0, c1, c2, c3, sub, s_a, s_psi, fast, off, t, r0, r1, r2, r3);

    if (valid) {
        if (!LAST) {
            *reinterpret_cast<ushort4*>(u_new + (size_t)q * KC + sub * 4) =
                enc_u(a0, a1, a2, a3);
            *reinterpret_cast<ushort4*>(u_new + ((size_t)q + E) * KC + sub * 4) =
                enc_u(c0, c1, c2, c3);
        }
        red_v4(Snext + (size_t)d * KC + sub * 4, m0, m1, m2, m3);
        red_v4(Snext + (size_t)s * KC + sub * 4, r0, r1, r2, r3);
    }
}

// beliefs: out = normalize(max(2^S4, EPS)); quad per node.
// Clamp-not-return so every warp stays fully convergent at the shuffles.
__global__ void belief_kernel(float* __restrict__ out, int n) {
    int gt  = blockIdx.x * blockDim.x + threadIdx.x;
    int i   = gt >> 2;
    int sub = threadIdx.x & 3;
    int valid = i < n;
    if (!valid) i = n - 1;
    float4 v = *reinterpret_cast<const float4*>(g_S[4] + (size_t)i * KC + sub * 4);
    float x0 = fmaxf(ex2f(v.x), BP_EPS);
    float x1 = fmaxf(ex2f(v.y), BP_EPS);
    float x2 = fmaxf(ex2f(v.z), BP_EPS);
    float x3 = fmaxf(ex2f(v.w), BP_EPS);
    float Z = quad_sum(x0 + x1 + x2 + x3);
    float r = 1.f / Z;
    if (valid)
        *reinterpret_cast<float4*>(out + (size_t)i * KC + sub * 4) =
            make_float4(x0 * r, x1 * r, x2 * r, x3 * r);
}

extern "C" void kernel_launch(void* const* d_in, const int* in_sizes, int n_in,
                              void* d_out, int out_size) {
    const float* prior  = (const float*)d_in[0];
    const float* logpsi = (const float*)d_in[1];
    const int*   src    = (const int*)d_in[2];
    const int*   dst    = (const int*)d_in[3];
    float* out = (float*)d_out;

    int n16 = in_sizes[0];      // n * 16
    int n   = n16 / KC;
    int e2  = in_sizes[2];      // directed edges
    int E   = e2 / 2;           // undirected pairs

    int gb_n    = (n + 255) / 256;
    int gb_e2   = (e2 + 255) / 256;
    int gb_pair = (E * 4 + 255) / 256;   // quad-per-pair grid
    int gb_nq   = (n * 4 + 255) / 256;

    // #0, #1: prelude
    prep_kernel<<<gb_n, 256>>>(logpsi, n);
    hist_init_kernel<<<gb_e2, 256>>>(dst, prior, e2, n16);

    // #2: iteration 1 — writes compressed uB, REDs into S1
    update_first_kernel<<<gb_pair, 256>>>(src, dst, prior, E);
    // #3: iteration 2 (steady; ncu capture lands here) — uB -> uA, S1 -> S2
    update_kernel<0, 0><<<gb_pair, 256>>>(src, dst, 1, E);
    // #4: iteration 3 — uA -> uB, S2 -> S3
    update_kernel<1, 0><<<gb_pair, 256>>>(src, dst, 2, E);
    // #5: iteration 4 — read uB, no store, S3 -> S4
    update_kernel<0, 1><<<gb_pair, 256>>>(src, dst, 3, E);

    // #6: beliefs
    belief_kernel<<<gb_nq, 256>>>(out, n);
}

// round 10
// speedup vs baseline: 1.6593x; 1.2190x over previous
#include <cuda_runtime.h>
#include <cstddef>

#define KC 16
#define NMAX 100000
#define E2MAX 3200000
#define BP_EPS 1e-12f

// Persistent scratch (device globals; no allocation allowed).
// Messages stored as m̂ = round(65536 * m / Z) in unorm16 (normalized message).
static __device__ unsigned short g_uA[(size_t)E2MAX * KC];  // 102.4 MB ping
static __device__ unsigned short g_uB[(size_t)E2MAX * KC];  // 102.4 MB pong
static __device__ float g_S[5][(size_t)NMAX * KC];          // node accumulators [1..4]
static __device__ int   g_deg[NMAX];                        // in-degree
static __device__ float g_psi[KC * KC];
static __device__ float g_acoef[KC];
static __device__ float g_off;
static __device__ int   g_fast;

__device__ __forceinline__ float ex2f(float x) {
    float y; asm("ex2.approx.f32 %0, %1;" : "=f"(y) : "f"(x)); return y;
}
__device__ __forceinline__ float lg2f_(float x) {
    float y; asm("lg2.approx.f32 %0, %1;" : "=f"(y) : "f"(x)); return y;
}
__device__ __forceinline__ void red_v4(float* p, float a, float b, float c, float d) {
    asm volatile("red.global.add.v4.f32 [%0], {%1, %2, %3, %4};"
                 :: "l"(p), "f"(a), "f"(b), "f"(c), "f"(d) : "memory");
}
__device__ __forceinline__ float quad_sum(float v) {
    v += __shfl_xor_sync(0xFFFFFFFFu, v, 1);
    v += __shfl_xor_sync(0xFFFFFFFFu, v, 2);
    return v;
}

// k0: block 0 computes psi tables; all blocks zero the degree histogram.
__global__ void prep_kernel(const float* __restrict__ logpsi, int n) {
    int t = threadIdx.x;
    if (blockIdx.x == 0) {
        __shared__ float psi[KC * KC];
        if (t < KC * KC) { float p = expf(logpsi[t]); psi[t] = p; g_psi[t] = p; }
        __syncthreads();
        if (t == 0) {
            float off = psi[1];
            int fast = 1;
            for (int i = 0; i < KC; i++)
                for (int j = 0; j < KC; j++)
                    if (i != j && psi[i * KC + j] != off) fast = 0;
            g_fast = fast;
            g_off = off;
            for (int c = 0; c < KC; c++) g_acoef[c] = psi[c * KC + c] - off;
        }
    }
    int i = blockIdx.x * blockDim.x + t;
    if (i < n) g_deg[i] = 0;
}

// k1: degree histogram + init S[1..4] = log2(prior)
__global__ void hist_init_kernel(const int* __restrict__ dst,
                                 const float* __restrict__ prior, int e2, int n16) {
    int i = blockIdx.x * blockDim.x + threadIdx.x;
    if (i < e2) atomicAdd(&g_deg[dst[i]], 1);
    if (i < n16) {
        float v = log2f(prior[i]);
        g_S[1][i] = v; g_S[2][i] = v; g_S[3][i] = v; g_S[4][i] = v;
    }
}

// Unnormalized message transform: m = b @ psi (fast: m_c = a_c*b_c + off*T),
// and Z = total sum (for normalization). Uniform control flow (shuffles inside).
__device__ __forceinline__ void msg_mz(
    float b0, float b1, float b2, float b3, int sub,
    const float* __restrict__ s_a, const float* __restrict__ s_psi,
    int fast, float off, int t,
    float& m0, float& m1, float& m2, float& m3, float& Z)
{
    if (fast) {
        float T = quad_sum(b0 + b1 + b2 + b3);
        float oT = off * T;
        m0 = fmaf(s_a[sub * 4 + 0], b0, oT);
        m1 = fmaf(s_a[sub * 4 + 1], b1, oT);
        m2 = fmaf(s_a[sub * 4 + 2], b2, oT);
        m3 = fmaf(s_a[sub * 4 + 3], b3, oT);
    } else {
        float bl[4] = {b0, b1, b2, b3};
        float acc[4] = {0.f, 0.f, 0.f, 0.f};
        #pragma unroll
        for (int j = 0; j < KC; j++) {
            int owner_sub = j >> 2;
            float bj = __shfl_sync(0xFFFFFFFFu, bl[j & 3], ((t & 31) & ~3) | owner_sub, 32);
            #pragma unroll
            for (int c = 0; c < 4; c++)
                acc[c] = fmaf(bj, s_psi[j * KC + sub * 4 + c], acc[c]);
        }
        m0 = acc[0]; m1 = acc[1]; m2 = acc[2]; m3 = acc[3];
    }
    Z = quad_sum(m0 + m1 + m2 + m3);
}

// Quantize m/Z to unorm16 and return the CONSISTENT log2 message values
// lm_c = lg2(m̂_c) - 16 (exactly what the next iteration reconstructs).
__device__ __forceinline__ ushort4 enc_lm(
    float m0, float m1, float m2, float m3, float Z,
    float& l0, float& l1, float& l2, float& l3)
{
    float r = __fdividef(65536.f, Z);
    unsigned q0 = __float2uint_rn(fminf(m0 * r, 65535.f));
    unsigned q1 = __float2uint_rn(fminf(m1 * r, 65535.f));
    unsigned q2 = __float2uint_rn(fminf(m2 * r, 65535.f));
    unsigned q3 = __float2uint_rn(fminf(m3 * r, 65535.f));
    l0 = lg2f_(__uint2float_rn(q0)) - 16.f;
    l1 = lg2f_(__uint2float_rn(q1)) - 16.f;
    l2 = lg2f_(__uint2float_rn(q2)) - 16.f;
    l3 = lg2f_(__uint2float_rn(q3)) - 16.f;
    return make_ushort4((unsigned short)q0, (unsigned short)q1,
                        (unsigned short)q2, (unsigned short)q3);
}

#define DEC_LM(u, l0, l1, l2, l3) \
    l0 = lg2f_(__uint2float_rn((unsigned)(u).x)) - 16.f; \
    l1 = lg2f_(__uint2float_rn((unsigned)(u).y)) - 16.f; \
    l2 = lg2f_(__uint2float_rn((unsigned)(u).z)) - 16.f; \
    l3 = lg2f_(__uint2float_rn((unsigned)(u).w)) - 16.f;

#define LOAD_TABLES() \
    __shared__ float s_psi[KC * KC]; \
    __shared__ float s_a[KC]; \
    __shared__ float s_off_sh; \
    __shared__ int   s_fast_sh; \
    { int tt = threadIdx.x; \
      if (tt < KC * KC) s_psi[tt] = g_psi[tt]; \
      if (tt < KC) s_a[tt] = g_acoef[tt]; \
      if (tt == 0) { s_off_sh = g_off; s_fast_sh = g_fast; } } \
    __syncthreads();

// k2: iteration 1. Pair (q, q+E) per quad. b1 = max(prior * 2^(4-4deg), EPS).
// Quantizes messages to uB and REDs the consistent lm into S[1].
__global__ void __launch_bounds__(256) update_first_kernel(
    const int* __restrict__ src, const int* __restrict__ dst,
    const float* __restrict__ prior, int E)
{
    LOAD_TABLES();
    int t = threadIdx.x;
    int gt = blockIdx.x * blockDim.x + t;
    int q = gt >> 2, sub = t & 3;
    int valid = q < E;
    if (!valid) q = E - 1;

    int s = src[q], d = dst[q];
    float4 Ps = *reinterpret_cast<const float4*>(prior + (size_t)s * KC + sub * 4);
    float4 Pd = *reinterpret_cast<const float4*>(prior + (size_t)d * KC + sub * 4);
    float ws = ex2f(fmaf((float)g_deg[s], -4.f, 4.f));
    float wd = ex2f(fmaf((float)g_deg[d], -4.f, 4.f));

    const int fast = s_fast_sh; const float off = s_off_sh;

    // e0 = q: s -> d
    float a0 = fmaxf(Ps.x * ws, BP_EPS), a1 = fmaxf(Ps.y * ws, BP_EPS);
    float a2 = fmaxf(Ps.z * ws, BP_EPS), a3 = fmaxf(Ps.w * ws, BP_EPS);
    float m0, m1, m2, m3, Zm;
    msg_mz(a0, a1, a2, a3, sub, s_a, s_psi, fast, off, t, m0, m1, m2, m3, Zm);

    // e1 = q+E: d -> s
    float c0 = fmaxf(Pd.x * wd, BP_EPS), c1 = fmaxf(Pd.y * wd, BP_EPS);
    float c2 = fmaxf(Pd.z * wd, BP_EPS), c3 = fmaxf(Pd.w * wd, BP_EPS);
    float r0, r1, r2, r3, Zr;
    msg_mz(c0, c1, c2, c3, sub, s_a, s_psi, fast, off, t, r0, r1, r2, r3, Zr);

    if (valid) {
        float lm0, lm1, lm2, lm3, ln0, ln1, ln2, ln3;
        ushort4 ue0 = enc_lm(m0, m1, m2, m3, Zm, lm0, lm1, lm2, lm3);
        ushort4 ue1 = enc_lm(r0, r1, r2, r3, Zr, ln0, ln1, ln2, ln3);
        *reinterpret_cast<ushort4*>(g_uB + (size_t)q * KC + sub * 4) = ue0;
        *reinterpret_cast<ushort4*>(g_uB + ((size_t)q + E) * KC + sub * 4) = ue1;
        red_v4(g_S[1] + (size_t)d * KC + sub * 4, lm0, lm1, lm2, lm3);
        red_v4(g_S[1] + (size_t)s * KC + sub * 4, ln0, ln1, ln2, ln3);
    }
}

// Steady iteration. AB=1: old=uA,new=uB. AB=0: old=uB,new=uA. LAST: no store,
// RED exact (unquantized) log messages into the final S.
template <int AB, int LAST>
__global__ void __launch_bounds__(256) update_kernel(
    const int* __restrict__ src, const int* __restrict__ dst, int sin_idx, int E)
{
    LOAD_TABLES();
    int t = threadIdx.x;
    int gt = blockIdx.x * blockDim.x + t;
    int q = gt >> 2, sub = t & 3;
    int valid = q < E;
    if (!valid) q = E - 1;

    const unsigned short* __restrict__ u_old = AB ? g_uA : g_uB;
    unsigned short* __restrict__       u_new = AB ? g_uB : g_uA;
    const float* __restrict__ Sin   = g_S[sin_idx];
    float* __restrict__       Snext = g_S[sin_idx + 1];

    int s = src[q], d = dst[q];

    ushort4 up0 = *reinterpret_cast<const ushort4*>(u_old + (size_t)q * KC + sub * 4);
    ushort4 up1 = *reinterpret_cast<const ushort4*>(u_old + ((size_t)q + E) * KC + sub * 4);
    float4 Ss = *reinterpret_cast<const float4*>(Sin + (size_t)s * KC + sub * 4);
    float4 Sd = *reinterpret_cast<const float4*>(Sin + (size_t)d * KC + sub * 4);

    const int fast = s_fast_sh; const float off = s_off_sh;

    // decode old log2 messages (exact values that were RED'd into Sin)
    float l00, l01, l02, l03;  // lm_old e0 (s->d)
    DEC_LM(up0, l00, l01, l02, l03);
    float l10, l11, l12, l13;  // lm_old e1 (d->s)
    DEC_LM(up1, l10, l11, l12, l13);

    // new message e0 = q (s->d): excludes reverse message (e1)
    float a0 = fmaxf(ex2f(Ss.x - l10), BP_EPS);
    float a1 = fmaxf(ex2f(Ss.y - l11), BP_EPS);
    float a2 = fmaxf(ex2f(Ss.z - l12), BP_EPS);
    float a3 = fmaxf(ex2f(Ss.w - l13), BP_EPS);
    float m0, m1, m2, m3, Zm;
    msg_mz(a0, a1, a2, a3, sub, s_a, s_psi, fast, off, t, m0, m1, m2, m3, Zm);

    // new message e1 = q+E (d->s): excludes reverse message (e0)
    float c0 = fmaxf(ex2f(Sd.x - l00), BP_EPS);
    float c1 = fmaxf(ex2f(Sd.y - l01), BP_EPS);
    float c2 = fmaxf(ex2f(Sd.z - l02), BP_EPS);
    float c3 = fmaxf(ex2f(Sd.w - l03), BP_EPS);
    float r0, r1, r2, r3, Zr;
    msg_mz(c0, c1, c2, c3, sub, s_a, s_psi, fast, off, t, r0, r1, r2, r3, Zr);

    if (valid) {
        if (!LAST) {
            float lm0, lm1, lm2, lm3, ln0, ln1, ln2, ln3;
            ushort4 ue0 = enc_lm(m0, m1, m2, m3, Zm, lm0, lm1, lm2, lm3);
            ushort4 ue1 = enc_lm(r0, r1, r2, r3, Zr, ln0, ln1, ln2, ln3);
            *reinterpret_cast<ushort4*>(u_new + (size_t)q * KC + sub * 4) = ue0;
            *reinterpret_cast<ushort4*>(u_new + ((size_t)q + E) * KC + sub * 4) = ue1;
            red_v4(Snext + (size_t)d * KC + sub * 4, lm0, lm1, lm2, lm3);
            red_v4(Snext + (size_t)s * KC + sub * 4, ln0, ln1, ln2, ln3);
        } else {
            float lZm = lg2f_(Zm), lZr = lg2f_(Zr);
            red_v4(Snext + (size_t)d * KC + sub * 4,
                   lg2f_(m0) - lZm, lg2f_(m1) - lZm, lg2f_(m2) - lZm, lg2f_(m3) - lZm);
            red_v4(Snext + (size_t)s * KC + sub * 4,
                   lg2f_(r0) - lZr, lg2f_(r1) - lZr, lg2f_(r2) - lZr, lg2f_(r3) - lZr);
        }
    }
}

// beliefs: out = normalize(max(2^S4, EPS)); quad per node, fully convergent.
__global__ void belief_kernel(float* __restrict__ out, int n) {
    int gt  = blockIdx.x * blockDim.x + threadIdx.x;
    int i   = gt >> 2;
    int sub = threadIdx.x & 3;
    int valid = i < n;
    if (!valid) i = n - 1;
    float4 v = *reinterpret_cast<const float4*>(g_S[4] + (size_t)i * KC + sub * 4);
    float x0 = fmaxf(ex2f(v.x), BP_EPS);
    float x1 = fmaxf(ex2f(v.y), BP_EPS);
    float x2 = fmaxf(ex2f(v.z), BP_EPS);
    float x3 = fmaxf(ex2f(v.w), BP_EPS);
    float Z = quad_sum(x0 + x1 + x2 + x3);
    float r = 1.f / Z;
    if (valid)
        *reinterpret_cast<float4*>(out + (size_t)i * KC + sub * 4) =
            make_float4(x0 * r, x1 * r, x2 * r, x3 * r);
}

extern "C" void kernel_launch(void* const* d_in, const int* in_sizes, int n_in,
                              void* d_out, int out_size) {
    const float* prior  = (const float*)d_in[0];
    const float* logpsi = (const float*)d_in[1];
    const int*   src    = (const int*)d_in[2];
    const int*   dst    = (const int*)d_in[3];
    float* out = (float*)d_out;

    int n16 = in_sizes[0];      // n * 16
    int n   = n16 / KC;
    int e2  = in_sizes[2];      // directed edges
    int E   = e2 / 2;           // undirected pairs

    int gb_n    = (n + 255) / 256;
    int gb_e2   = (e2 + 255) / 256;
    int gb_pair = (E * 4 + 255) / 256;   // quad-per-pair grid
    int gb_nq   = (n * 4 + 255) / 256;

    // #0, #1: prelude
    prep_kernel<<<gb_n, 256>>>(logpsi, n);
    hist_init_kernel<<<gb_e2, 256>>>(dst, prior, e2, n16);

    // #2: iteration 1 — writes quantized uB, REDs consistent lm into S1
    update_first_kernel<<<gb_pair, 256>>>(src, dst, prior, E);
    // #3: iteration 2 (steady; ncu capture lands here) — uB -> uA, S1 -> S2
    update_kernel<0, 0><<<gb_pair, 256>>>(src, dst, 1, E);
    // #4: iteration 3 — uA -> uB, S2 -> S3
    update_kernel<1, 0><<<gb_pair, 256>>>(src, dst, 2, E);
    // #5: iteration 4 — read uB, no store, exact lm REDs, S3 -> S4
    update_kernel<0, 1><<<gb_pair, 256>>>(src, dst, 3, E);

    // #6: beliefs
    belief_kernel<<<gb_nq, 256>>>(out, n);
}

// round 11
// speedup vs baseline: 1.7812x; 1.0735x over previous
#include <cuda_runtime.h>
#include <cstddef>

#define KC 16
#define NMAX 100000
#define E2MAX 3200000
#define BP_EPS 1e-12f

// Persistent scratch (device globals; no allocation allowed).
// Messages stored as m̂ = round(65536 * m / Z) in unorm16 (normalized message).
static __device__ unsigned short g_uA[(size_t)E2MAX * KC];  // 102.4 MB ping
static __device__ unsigned short g_uB[(size_t)E2MAX * KC];  // 102.4 MB pong
static __device__ float g_S[5][(size_t)NMAX * KC];          // node accumulators [1..4]
static __device__ int   g_deg[NMAX];                        // in-degree
static __device__ float g_psi[KC * KC];
static __device__ float g_acoef[KC];
static __device__ float g_off;
static __device__ float g_adiag;   // uniform diagonal coefficient (fast2)
static __device__ float g_kz;      // Z = kz * T when fast2
static __device__ int   g_fast;    // diag-plus-constant psi
static __device__ int   g_fast2;   // ... with uniform diagonal

__device__ __forceinline__ float ex2f(float x) {
    float y; asm("ex2.approx.f32 %0, %1;" : "=f"(y) : "f"(x)); return y;
}
__device__ __forceinline__ float lg2f_(float x) {
    float y; asm("lg2.approx.f32 %0, %1;" : "=f"(y) : "f"(x)); return y;
}
__device__ __forceinline__ void red_v4(float* p, float a, float b, float c, float d) {
    asm volatile("red.global.add.v4.f32 [%0], {%1, %2, %3, %4};"
                 :: "l"(p), "f"(a), "f"(b), "f"(c), "f"(d) : "memory");
}
__device__ __forceinline__ float quad_sum(float v) {
    v += __shfl_xor_sync(0xFFFFFFFFu, v, 1);
    v += __shfl_xor_sync(0xFFFFFFFFu, v, 2);
    return v;
}

// k0: block 0 computes psi tables; all blocks zero the degree histogram.
__global__ void prep_kernel(const float* __restrict__ logpsi, int n) {
    int t = threadIdx.x;
    if (blockIdx.x == 0) {
        __shared__ float psi[KC * KC];
        if (t < KC * KC) { float p = expf(logpsi[t]); psi[t] = p; g_psi[t] = p; }
        __syncthreads();
        if (t == 0) {
            float off = psi[1];
            int fast = 1;
            for (int i = 0; i < KC; i++)
                for (int j = 0; j < KC; j++)
                    if (i != j && psi[i * KC + j] != off) fast = 0;
            int fast2 = fast;
            float dia = psi[0];
            for (int c = 1; c < KC; c++)
                if (psi[c * KC + c] != dia) fast2 = 0;
            g_fast = fast;
            g_fast2 = fast2;
            g_off = off;
            g_adiag = dia - off;
            g_kz = (dia - off) + 16.f * off;
            for (int c = 0; c < KC; c++) g_acoef[c] = psi[c * KC + c] - off;
        }
    }
    int i = blockIdx.x * blockDim.x + t;
    if (i < n) g_deg[i] = 0;
}

// k1: degree histogram + init S[1..4] = log2(prior)
__global__ void hist_init_kernel(const int* __restrict__ dst,
                                 const float* __restrict__ prior, int e2, int n16) {
    int i = blockIdx.x * blockDim.x + threadIdx.x;
    if (i < e2) atomicAdd(&g_deg[dst[i]], 1);
    if (i < n16) {
        float v = log2f(prior[i]);
        g_S[1][i] = v; g_S[2][i] = v; g_S[3][i] = v; g_S[4][i] = v;
    }
}

// Unnormalized message transform: m = b @ psi and Z = total sum.
// fast2: uniform diagonal -> Z = kz * T (no second quad_sum).
__device__ __forceinline__ void msg_mz(
    float b0, float b1, float b2, float b3, int sub,
    const float* __restrict__ s_a, const float* __restrict__ s_psi,
    int fast, int fast2, float off, float adiag, float kz, int t,
    float& m0, float& m1, float& m2, float& m3, float& Z)
{
    if (fast2) {
        float T = quad_sum(b0 + b1 + b2 + b3);
        float oT = off * T;
        m0 = fmaf(adiag, b0, oT);
        m1 = fmaf(adiag, b1, oT);
        m2 = fmaf(adiag, b2, oT);
        m3 = fmaf(adiag, b3, oT);
        Z = kz * T;
    } else if (fast) {
        float T = quad_sum(b0 + b1 + b2 + b3);
        float oT = off * T;
        m0 = fmaf(s_a[sub * 4 + 0], b0, oT);
        m1 = fmaf(s_a[sub * 4 + 1], b1, oT);
        m2 = fmaf(s_a[sub * 4 + 2], b2, oT);
        m3 = fmaf(s_a[sub * 4 + 3], b3, oT);
        Z = quad_sum(m0 + m1 + m2 + m3);
    } else {
        float bl[4] = {b0, b1, b2, b3};
        float acc[4] = {0.f, 0.f, 0.f, 0.f};
        #pragma unroll
        for (int j = 0; j < KC; j++) {
            int owner_sub = j >> 2;
            float bj = __shfl_sync(0xFFFFFFFFu, bl[j & 3], ((t & 31) & ~3) | owner_sub, 32);
            #pragma unroll
            for (int c = 0; c < 4; c++)
                acc[c] = fmaf(bj, s_psi[j * KC + sub * 4 + c], acc[c]);
        }
        m0 = acc[0]; m1 = acc[1]; m2 = acc[2]; m3 = acc[3];
        Z = quad_sum(m0 + m1 + m2 + m3);
    }
}

// Quantize m/Z to unorm16 and return the CONSISTENT log2 message values
// lm_c = lg2(m̂_c) - 16 (exactly what the next iteration reconstructs).
__device__ __forceinline__ ushort4 enc_lm(
    float m0, float m1, float m2, float m3, float Z,
    float& l0, float& l1, float& l2, float& l3)
{
    float r = __fdividef(65536.f, Z);
    unsigned q0 = __float2uint_rn(fminf(m0 * r, 65535.f));
    unsigned q1 = __float2uint_rn(fminf(m1 * r, 65535.f));
    unsigned q2 = __float2uint_rn(fminf(m2 * r, 65535.f));
    unsigned q3 = __float2uint_rn(fminf(m3 * r, 65535.f));
    l0 = lg2f_(__uint2float_rn(q0)) - 16.f;
    l1 = lg2f_(__uint2float_rn(q1)) - 16.f;
    l2 = lg2f_(__uint2float_rn(q2)) - 16.f;
    l3 = lg2f_(__uint2float_rn(q3)) - 16.f;
    return make_ushort4((unsigned short)q0, (unsigned short)q1,
                        (unsigned short)q2, (unsigned short)q3);
}

#define DEC_LM(u, l0, l1, l2, l3) \
    l0 = lg2f_(__uint2float_rn((unsigned)(u).x)) - 16.f; \
    l1 = lg2f_(__uint2float_rn((unsigned)(u).y)) - 16.f; \
    l2 = lg2f_(__uint2float_rn((unsigned)(u).z)) - 16.f; \
    l3 = lg2f_(__uint2float_rn((unsigned)(u).w)) - 16.f;

#define LOAD_TABLES() \
    __shared__ float s_psi[KC * KC]; \
    __shared__ float s_a[KC]; \
    __shared__ float s_off_sh, s_adiag_sh, s_kz_sh; \
    __shared__ int   s_fast_sh, s_fast2_sh; \
    { int tt = threadIdx.x; \
      if (tt < KC * KC) s_psi[tt] = g_psi[tt]; \
      if (tt < KC) s_a[tt] = g_acoef[tt]; \
      if (tt == 0) { s_off_sh = g_off; s_fast_sh = g_fast; \
                     s_fast2_sh = g_fast2; s_adiag_sh = g_adiag; s_kz_sh = g_kz; } } \
    __syncthreads(); \
    const int fast = s_fast_sh, fast2 = s_fast2_sh; \
    const float off = s_off_sh, adiag = s_adiag_sh, kz = s_kz_sh;

// k2: iteration 1. Pair (q, q+E) per quad. b1 = max(prior * 2^(4-4deg), EPS).
// Quantizes messages to uB and REDs the consistent lm into S[1].
__global__ void __launch_bounds__(256, 6) update_first_kernel(
    const int* __restrict__ src, const int* __restrict__ dst,
    const float* __restrict__ prior, int E)
{
    LOAD_TABLES();
    int t = threadIdx.x;
    int gt = blockIdx.x * blockDim.x + t;
    int q = gt >> 2, sub = t & 3;
    int valid = q < E;
    if (!valid) q = E - 1;

    int s = src[q], d = dst[q];
    float4 Ps = *reinterpret_cast<const float4*>(prior + (size_t)s * KC + sub * 4);
    float4 Pd = *reinterpret_cast<const float4*>(prior + (size_t)d * KC + sub * 4);
    float ws = ex2f(fmaf((float)g_deg[s], -4.f, 4.f));
    float wd = ex2f(fmaf((float)g_deg[d], -4.f, 4.f));

    // e0 = q: s -> d
    float a0 = fmaxf(Ps.x * ws, BP_EPS), a1 = fmaxf(Ps.y * ws, BP_EPS);
    float a2 = fmaxf(Ps.z * ws, BP_EPS), a3 = fmaxf(Ps.w * ws, BP_EPS);
    float m0, m1, m2, m3, Zm;
    msg_mz(a0, a1, a2, a3, sub, s_a, s_psi, fast, fast2, off, adiag, kz, t,
           m0, m1, m2, m3, Zm);

    // e1 = q+E: d -> s
    float c0 = fmaxf(Pd.x * wd, BP_EPS), c1 = fmaxf(Pd.y * wd, BP_EPS);
    float c2 = fmaxf(Pd.z * wd, BP_EPS), c3 = fmaxf(Pd.w * wd, BP_EPS);
    float r0, r1, r2, r3, Zr;
    msg_mz(c0, c1, c2, c3, sub, s_a, s_psi, fast, fast2, off, adiag, kz, t,
           r0, r1, r2, r3, Zr);

    if (valid) {
        float lm0, lm1, lm2, lm3, ln0, ln1, ln2, ln3;
        ushort4 ue0 = enc_lm(m0, m1, m2, m3, Zm, lm0, lm1, lm2, lm3);
        ushort4 ue1 = enc_lm(r0, r1, r2, r3, Zr, ln0, ln1, ln2, ln3);
        *reinterpret_cast<ushort4*>(g_uB + (size_t)q * KC + sub * 4) = ue0;
        *reinterpret_cast<ushort4*>(g_uB + ((size_t)q + E) * KC + sub * 4) = ue1;
        red_v4(g_S[1] + (size_t)d * KC + sub * 4, lm0, lm1, lm2, lm3);
        red_v4(g_S[1] + (size_t)s * KC + sub * 4, ln0, ln1, ln2, ln3);
    }
}

// Steady iteration. AB=1: old=uA,new=uB. AB=0: old=uB,new=uA. LAST: no store,
// RED exact (unquantized) log messages into the final S.
template <int AB, int LAST>
__global__ void __launch_bounds__(256, 6) update_kernel(
    const int* __restrict__ src, const int* __restrict__ dst, int sin_idx, int E)
{
    LOAD_TABLES();
    int t = threadIdx.x;
    int gt = blockIdx.x * blockDim.x + t;
    int q = gt >> 2, sub = t & 3;
    int valid = q < E;
    if (!valid) q = E - 1;

    const unsigned short* __restrict__ u_old = AB ? g_uA : g_uB;
    unsigned short* __restrict__       u_new = AB ? g_uB : g_uA;
    const float* __restrict__ Sin   = g_S[sin_idx];
    float* __restrict__       Snext = g_S[sin_idx + 1];

    int s = src[q], d = dst[q];

    ushort4 up0 = *reinterpret_cast<const ushort4*>(u_old + (size_t)q * KC + sub * 4);
    ushort4 up1 = *reinterpret_cast<const ushort4*>(u_old + ((size_t)q + E) * KC + sub * 4);
    float4 Ss = *reinterpret_cast<const float4*>(Sin + (size_t)s * KC + sub * 4);
    float4 Sd = *reinterpret_cast<const float4*>(Sin + (size_t)d * KC + sub * 4);

    // decode old log2 messages (exact values that were RED'd into Sin)
    float l00, l01, l02, l03;  // lm_old e0 (s->d)
    DEC_LM(up0, l00, l01, l02, l03);
    float l10, l11, l12, l13;  // lm_old e1 (d->s)
    DEC_LM(up1, l10, l11, l12, l13);

    // new message e0 = q (s->d): excludes reverse message (e1)
    float a0 = fmaxf(ex2f(Ss.x - l10), BP_EPS);
    float a1 = fmaxf(ex2f(Ss.y - l11), BP_EPS);
    float a2 = fmaxf(ex2f(Ss.z - l12), BP_EPS);
    float a3 = fmaxf(ex2f(Ss.w - l13), BP_EPS);
    float m0, m1, m2, m3, Zm;
    msg_mz(a0, a1, a2, a3, sub, s_a, s_psi, fast, fast2, off, adiag, kz, t,
           m0, m1, m2, m3, Zm);

    // new message e1 = q+E (d->s): excludes reverse message (e0)
    float c0 = fmaxf(ex2f(Sd.x - l00), BP_EPS);
    float c1 = fmaxf(ex2f(Sd.y - l01), BP_EPS);
    float c2 = fmaxf(ex2f(Sd.z - l02), BP_EPS);
    float c3 = fmaxf(ex2f(Sd.w - l03), BP_EPS);
    float r0, r1, r2, r3, Zr;
    msg_mz(c0, c1, c2, c3, sub, s_a, s_psi, fast, fast2, off, adiag, kz, t,
           r0, r1, r2, r3, Zr);

    if (valid) {
        if (!LAST) {
            float lm0, lm1, lm2, lm3, ln0, ln1, ln2, ln3;
            ushort4 ue0 = enc_lm(m0, m1, m2, m3, Zm, lm0, lm1, lm2, lm3);
            ushort4 ue1 = enc_lm(r0, r1, r2, r3, Zr, ln0, ln1, ln2, ln3);
            *reinterpret_cast<ushort4*>(u_new + (size_t)q * KC + sub * 4) = ue0;
            *reinterpret_cast<ushort4*>(u_new + ((size_t)q + E) * KC + sub * 4) = ue1;
            red_v4(Snext + (size_t)d * KC + sub * 4, lm0, lm1, lm2, lm3);
            red_v4(Snext + (size_t)s * KC + sub * 4, ln0, ln1, ln2, ln3);
        } else {
            float lZm = lg2f_(Zm), lZr = lg2f_(Zr);
            red_v4(Snext + (size_t)d * KC + sub * 4,
                   lg2f_(m0) - lZm, lg2f_(m1) - lZm, lg2f_(m2) - lZm, lg2f_(m3) - lZm);
            red_v4(Snext + (size_t)s * KC + sub * 4,
                   lg2f_(r0) - lZr, lg2f_(r1) - lZr, lg2f_(r2) - lZr, lg2f_(r3) - lZr);
        }
    }
}

// beliefs: out = normalize(max(2^S4, EPS)); quad per node, fully convergent.
__global__ void belief_kernel(float* __restrict__ out, int n) {
    int gt  = blockIdx.x * blockDim.x + threadIdx.x;
    int i   = gt >> 2;
    int sub = threadIdx.x & 3;
    int valid = i < n;
    if (!valid) i = n - 1;
    float4 v = *reinterpret_cast<const float4*>(g_S[4] + (size_t)i * KC + sub * 4);
    float x0 = fmaxf(ex2f(v.x), BP_EPS);
    float x1 = fmaxf(ex2f(v.y), BP_EPS);
    float x2 = fmaxf(ex2f(v.z), BP_EPS);
    float x3 = fmaxf(ex2f(v.w), BP_EPS);
    float Z = quad_sum(x0 + x1 + x2 + x3);
    float r = 1.f / Z;
    if (valid)
        *reinterpret_cast<float4*>(out + (size_t)i * KC + sub * 4) =
            make_float4(x0 * r, x1 * r, x2 * r, x3 * r);
}

extern "C" void kernel_launch(void* const* d_in, const int* in_sizes, int n_in,
                              void* d_out, int out_size) {
    const float* prior  = (const float*)d_in[0];
    const float* logpsi = (const float*)d_in[1];
    const int*   src    = (const int*)d_in[2];
    const int*   dst    = (const int*)d_in[3];
    float* out = (float*)d_out;

    int n16 = in_sizes[0];      // n * 16
    int n   = n16 / KC;
    int e2  = in_sizes[2];      // directed edges
    int E   = e2 / 2;           // undirected pairs

    int gb_n    = (n + 255) / 256;
    int gb_e2   = (e2 + 255) / 256;
    int gb_pair = (E * 4 + 255) / 256;   // quad-per-pair grid
    int gb_nq   = (n * 4 + 255) / 256;

    // #0, #1: prelude
    prep_kernel<<<gb_n, 256>>>(logpsi, n);
    hist_init_kernel<<<gb_e2, 256>>>(dst, prior, e2, n16);

    // #2: iteration 1 — writes quantized uB, REDs consistent lm into S1
    update_first_kernel<<<gb_pair, 256>>>(src, dst, prior, E);
    // #3: iteration 2 (steady; ncu capture lands here) — uB -> uA, S1 -> S2
    update_kernel<0, 0><<<gb_pair, 256>>>(src, dst, 1, E);
    // #4: iteration 3 — uA -> uB, S2 -> S3
    update_kernel<1, 0><<<gb_pair, 256>>>(src, dst, 2, E);
    // #5: iteration 4 — read uB, no store, exact lm REDs, S3 -> S4
    update_kernel<0, 1><<<gb_pair, 256>>>(src, dst, 3, E);

    // #6: beliefs
    belief_kernel<<<gb_nq, 256>>>(out, n);
}